// round 16
// baseline (speedup 1.0000x reference)
#include <cuda_runtime.h>
#include <cuda_bf16.h>
#include <cstdint>

#define NB 4
#define NN 256
#define HH 128
typedef unsigned long long ull;

__device__ float g_A[NB*NN*HH];
__device__ float g_Bv[NB*NN*HH];

// smem byte offsets (pair_gemm, j-tile 128, 512 threads)
#define OFF_W    0          // Wt image [128 h][288 k] bf16 swizzled, stride 576B (73728B)
#define OFF_XJ   73728      // Xj bf16 pairs u32 [64 kp][136 stride] (34816B)
#define OFF_BJ   108544     // Bj bf16 pairs u32 [128 j][66]         (33792B)
#define OFF_HIS  142336     // hi bf16 pairs u32 [64]                (256B)
#define OFF_AI   142592     // f32[128]
#define OFF_W2   143104     // f32[128]
#define OFF_SCF  143616     // u32 [128 j][2]                        (1024B)
#define OFF_RED  144640     // f32[128 j][4 ch]                      (2048B)
#define SMEM_TOT 146688

__device__ __forceinline__ uint32_t s32(const void* p){
  uint32_t a; asm("{ .reg .u64 t; cvta.to.shared.u64 t, %1; cvt.u32.u64 %0, t; }":"=r"(a):"l"(p)); return a;
}
__device__ __forceinline__ uint32_t foff(uint32_t r, uint32_t k){
  return ((r*576u + k*2u) ^ ((r&7u)<<4));
}
__device__ __forceinline__ uint32_t f2bf(float a,float b){
  __nv_bfloat162 t=__floats2bfloat162_rn(a,b); return *(uint32_t*)&t;
}
__device__ __forceinline__ uint32_t habsub2(uint32_t h,uint32_t x){
  __nv_bfloat162 r=__habs2(__hsub2(*(__nv_bfloat162*)&h,*(__nv_bfloat162*)&x));
  return *(uint32_t*)&r;
}
__device__ __forceinline__ uint32_t hmul2u(uint32_t h,uint32_t x){
  __nv_bfloat162 r=__hmul2(*(__nv_bfloat162*)&h,*(__nv_bfloat162*)&x);
  return *(uint32_t*)&r;
}
__device__ __forceinline__ void cpa16(void* dst,const void* src){
  unsigned d=(unsigned)__cvta_generic_to_shared(dst);
  asm volatile("cp.async.cg.shared.global [%0],[%1],16;\n"::"r"(d),"l"(src));
}
__device__ __forceinline__ void cpcommit(){ asm volatile("cp.async.commit_group;\n"); }

#define LDSM4(r0,r1,r2,r3,a) asm volatile( \
  "ldmatrix.sync.aligned.m8n8.x4.shared.b16 {%0,%1,%2,%3},[%4];" \
  :"=r"(r0),"=r"(r1),"=r"(r2),"=r"(r3):"r"(a))
#define MMA16816(c,a,b) asm volatile( \
  "mma.sync.aligned.m16n8k16.row.col.f32.bf16.bf16.f32 " \
  "{%0,%1,%2,%3},{%4,%5,%6,%7},{%8,%9},{%0,%1,%2,%3};" \
  :"+f"((c)[0]),"+f"((c)[1]),"+f"((c)[2]),"+f"((c)[3]) \
  :"r"((a)[0]),"r"((a)[1]),"r"((a)[2]),"r"((a)[3]),"r"((b)[0]),"r"((b)[1]))

extern __shared__ __align__(1024) char dynsm[];

// ---- Kernel 1: per-node halves (validated) ----
#define PRE_SMEM (4*HH*4 + 2*2*32*HH*4)
__global__ void __launch_bounds__(256)
precompute_ab(const float* __restrict__ X,
              const float* __restrict__ W1,
              const float* __restrict__ b1){
  float* Xs=(float*)dynsm;
  float* Ws=(float*)(dynsm+4*HH*4);
  int r0=blockIdx.x*4;
  int tid=threadIdx.x;
  int h=tid&127, s=tid>>7;

  for(int e=tid;e<4*HH/4;e+=256)
    ((float4*)Xs)[e]=((const float4*)(X+(size_t)r0*HH))[e];

  #define STAGE(c,buf) do{ \
    for(int e=tid;e<2*32*HH/4;e+=256){ \
      int sh=e>=(32*HH/4); int le=e-sh*(32*HH/4); \
      cpa16((float4*)(Ws+(buf)*2*32*HH+sh*32*HH)+le, \
            (const float4*)(W1+((size_t)(sh*HH+(c)*32))*HH)+le); \
    } cpcommit(); }while(0)

  STAGE(0,0);
  float acc[4]={0.f,0.f,0.f,0.f};
  for(int c=0;c<4;c++){
    if(c<3){ STAGE(c+1,(c+1)&1); asm volatile("cp.async.wait_group 1;\n"); }
    else   { asm volatile("cp.async.wait_group 0;\n"); }
    __syncthreads();
    const float* wp=Ws+(c&1)*2*32*HH+s*32*HH;
#pragma unroll 8
    for(int kk=0;kk<32;kk++){
      float wv=wp[kk*HH+h];
      int k=c*32+kk;
#pragma unroll
      for(int r=0;r<4;r++) acc[r]+=Xs[r*HH+k]*wv;
    }
    __syncthreads();
  }
  if(s==0){
    float bb=b1[h];
#pragma unroll
    for(int r=0;r<4;r++) g_A[(size_t)(r0+r)*HH+h]=acc[r]+bb;
  } else {
#pragma unroll
    for(int r=0;r<4;r++) g_Bv[(size_t)(r0+r)*HH+h]=acc[r];
  }
  #undef STAGE
}

// ---- Kernel 2: bf16 HMMA GEMM, 512 threads (16 warps), j-tile 128 ----
__global__ void __launch_bounds__(512,1)
pair_gemm(const float* __restrict__ X,const float* __restrict__ base,
          const float* __restrict__ comp,const float* __restrict__ W1,
          const float* __restrict__ W2,const float* __restrict__ b2,
          float* __restrict__ out){
  char* sm=dynsm;
  uint32_t smb=s32(sm);
  int tid=threadIdx.x, w=tid>>5, lane=tid&31;
  int jt=blockIdx.x, ig=blockIdx.y, b=blockIdx.z;
  int j0=jt*128;
  int jw=(w&3)*32, hww=(w>>2)*32;
  int qr=lane>>2, tql=lane&3;
  float b2v=b2[0];

  // ---- once: W image (bf16, swizzled) ----
  {
    int h=tid&127, q4=tid>>7;                  // 4 quarters of k
    for(int c8=0;c8<8;c8++){
      int k0=q4*64+c8*8;
      uint32_t v[4];
#pragma unroll
      for(int q=0;q<4;q++)
        v[q]=f2bf(W1[(256+k0+2*q)*HH+h], W1[(256+k0+2*q+1)*HH+h]);
      *(float4*)(sm+OFF_W+foff(h,k0))=*(float4*)v;
    }
    if(tid<128){
      uint32_t v[4]={f2bf(W1[512*HH+h],W1[513*HH+h]),
                     f2bf(W1[514*HH+h],W1[515*HH+h]),0u,0u};
      *(float4*)(sm+OFF_W+foff(h,256))=*(float4*)v;
      uint32_t z[4]={0u,0u,0u,0u};
      *(float4*)(sm+OFF_W+foff(h,264))=*(float4*)z;
    }
  }
  // ---- once: Xj pairs [kp][j] stride 136, Bj pairs [j][hp] stride 66 ----
  for(int idx=tid;idx<64*128;idx+=512){
    int kp=idx&63, j=idx>>6;
    float2 xv=*(const float2*)(X+(size_t)(b*NN+j0+j)*HH+2*kp);
    *(uint32_t*)(sm+OFF_XJ+(kp*136+j)*4)=f2bf(xv.x,xv.y);
  }
  for(int idx=tid;idx<64*128;idx+=512){
    int hp=idx&63, j=idx>>6;
    float2 bv=*(const float2*)(g_Bv+(size_t)(b*NN+j0+j)*HH+2*hp);
    *(uint32_t*)(sm+OFF_BJ+(j*66+hp)*4)=f2bf(bv.x,bv.y);
  }
  if(tid<32) ((float4*)(sm+OFF_W2))[tid]=((const float4*)W2)[tid];

  // ---- stage first i: HIS, AI, SCF ----
  {
    int i=ig*16;
    if(tid<64){
      float2 xv=*(const float2*)(X+(size_t)(b*NN+i)*HH+2*tid);
      *(uint32_t*)(sm+OFF_HIS+tid*4)=f2bf(xv.x,xv.y);
    } else if(tid<96){
      ((float4*)(sm+OFF_AI))[tid-64]=((const float4*)(g_A+(size_t)(b*NN+i)*HH))[tid-64];
    } else if(tid>=128&&tid<256){
      int j=tid-128;
      float bv=fminf(fmaxf(base[((size_t)(b*NN)+i)*NN+j0+j],-20.f),20.f);
      float cv=fminf(fmaxf(comp[((size_t)(b*NN)+i)*NN+j0+j],-20.f),20.f);
      float sb=1.f/(1.f+__expf(-bv)), sc=1.f/(1.f+__expf(-cv));
      *(uint32_t*)(sm+OFF_SCF+(j*2+0)*4)=f2bf(bv,sb);
      *(uint32_t*)(sm+OFF_SCF+(j*2+1)*4)=f2bf(cv,sc);
    }
  }
  __syncthreads();

  uint32_t xr=(uint32_t)((lane&7)<<4);
  uint32_t offB[2];
#pragma unroll
  for(int q=0;q<2;q++){
    uint32_t rB=(uint32_t)(hww + q*16 + (lane&7) + ((lane>>4)<<3));
    offB[q]= OFF_W + rB*576u + (uint32_t)(((lane>>3)&1)*16);
  }

  float2 w24[4];
#pragma unroll
  for(int nt=0;nt<4;nt++)
    w24[nt]=*(float2*)(sm+OFF_W2+(hww+nt*8+2*tql)*4);

  for(int itn=0;itn<16;itn++){
    int i=ig*16+itn;

    float c[2][4][4];
#pragma unroll
    for(int mt=0;mt<2;mt++)
#pragma unroll
      for(int nt=0;nt<4;nt++)
#pragma unroll
        for(int e=0;e<4;e++) c[mt][nt][e]=0.f;

    uint32_t a[2][2][4], bfr[2][4][2];

    // A-fragment for main k-step ks (0..15): pairs wrap at 64
    #define MAKEA(ks,buf) do{ \
      int kp0=8*((ks)&7)+tql; \
      uint32_t h0=*(uint32_t*)(sm+OFF_HIS+kp0*4); \
      uint32_t h1=*(uint32_t*)(sm+OFF_HIS+(kp0+4)*4); \
      _Pragma("unroll") \
      for(int mt=0;mt<2;mt++){ \
        int r=jw+qr+mt*16; \
        uint32_t x0=*(uint32_t*)(sm+OFF_XJ+(kp0*136+r)*4); \
        uint32_t x1=*(uint32_t*)(sm+OFF_XJ+(kp0*136+r+8)*4); \
        uint32_t x2=*(uint32_t*)(sm+OFF_XJ+((kp0+4)*136+r)*4); \
        uint32_t x3=*(uint32_t*)(sm+OFF_XJ+((kp0+4)*136+r+8)*4); \
        if((ks)<8){ \
          a[buf][mt][0]=habsub2(h0,x0); a[buf][mt][1]=habsub2(h0,x1); \
          a[buf][mt][2]=habsub2(h1,x2); a[buf][mt][3]=habsub2(h1,x3); \
        } else { \
          a[buf][mt][0]=hmul2u(h0,x0); a[buf][mt][1]=hmul2u(h0,x1); \
          a[buf][mt][2]=hmul2u(h1,x2); a[buf][mt][3]=hmul2u(h1,x3); \
        } \
      } \
    }while(0)

    #define MAKEA16(buf) do{ \
      _Pragma("unroll") \
      for(int mt=0;mt<2;mt++){ \
        int r=jw+qr+mt*16; \
        a[buf][mt][0]=(tql<2)?*(uint32_t*)(sm+OFF_SCF+(r*2+tql)*4):0u; \
        a[buf][mt][1]=(tql<2)?*(uint32_t*)(sm+OFF_SCF+((r+8)*2+tql)*4):0u; \
        a[buf][mt][2]=0u; a[buf][mt][3]=0u; \
      } \
    }while(0)

    #define LOADB(ks,buf) do{ uint32_t k2=(uint32_t)(ks)*32u; \
      LDSM4(bfr[buf][0][0],bfr[buf][0][1],bfr[buf][1][0],bfr[buf][1][1], smb+((offB[0]+k2)^xr)); \
      LDSM4(bfr[buf][2][0],bfr[buf][2][1],bfr[buf][3][0],bfr[buf][3][1], smb+((offB[1]+k2)^xr)); \
    }while(0)

    MAKEA(0,0);
    LOADB(0,0);
#pragma unroll
    for(int ks=0;ks<17;ks++){
      int cur=ks&1, nxt=cur^1;
      if(ks<15)       MAKEA(ks+1,nxt);
      else if(ks==15) MAKEA16(nxt);
      if(ks<16)       LOADB(ks+1,nxt);
#pragma unroll
      for(int mt=0;mt<2;mt++)
#pragma unroll
        for(int nt=0;nt<4;nt++)
          MMA16816(c[mt][nt],a[cur][mt],bfr[cur][nt]);
    }
    #undef MAKEA
    #undef MAKEA16
    #undef LOADB

    // epilogue
    {
      int ch=w>>2;   // 0..3 h-chunk
      float2 ai4[4];
#pragma unroll
      for(int nt=0;nt<4;nt++)
        ai4[nt]=*(float2*)(sm+OFF_AI+(hww+nt*8+2*tql)*4);
      float p[4];
#pragma unroll
      for(int r=0;r<4;r++) p[r]=0.f;
#pragma unroll
      for(int mt=0;mt<2;mt++){
#pragma unroll
        for(int rh=0;rh<2;rh++){
          int j=jw+mt*16+rh*8+qr;
#pragma unroll
          for(int nt=0;nt<4;nt++){
            int hb=hww+nt*8+2*tql;
            float2 bj=__bfloat1622float2(*(__nv_bfloat162*)(sm+OFF_BJ+(j*66+(hb>>1))*4));
            p[mt*2+rh]+=fmaxf(c[mt][nt][rh*2]  +ai4[nt].x+bj.x,0.f)*w24[nt].x
                       +fmaxf(c[mt][nt][rh*2+1]+ai4[nt].y+bj.y,0.f)*w24[nt].y;
          }
        }
      }
#pragma unroll
      for(int r=0;r<4;r++){
        p[r]+=__shfl_xor_sync(0xffffffffu,p[r],1);
        p[r]+=__shfl_xor_sync(0xffffffffu,p[r],2);
      }
      if(tql==0){
#pragma unroll
        for(int r=0;r<4;r++){
          int j=jw+(r>>1)*16+(r&1)*8+qr;
          *(float*)(sm+OFF_RED+(j*4+ch)*4)=p[r];
        }
      }
    }
    __syncthreads();

    // writeback(i) + stage(i+1) (disjoint thread groups / smem regions)
    if(tid<128){
      float4 rv=*(float4*)(sm+OFF_RED+tid*16);
      out[((size_t)(b*NN)+i)*NN+j0+tid]=rv.x+rv.y+rv.z+rv.w+b2v;
    }
    if(itn<15){
      int i2=i+1;
      if(tid>=128&&tid<192){
        int t=tid-128;
        float2 xv=*(const float2*)(X+(size_t)(b*NN+i2)*HH+2*t);
        *(uint32_t*)(sm+OFF_HIS+t*4)=f2bf(xv.x,xv.y);
      } else if(tid>=192&&tid<224){
        ((float4*)(sm+OFF_AI))[tid-192]=((const float4*)(g_A+(size_t)(b*NN+i2)*HH))[tid-192];
      } else if(tid>=256&&tid<384){
        int j=tid-256;
        float bv=fminf(fmaxf(base[((size_t)(b*NN)+i2)*NN+j0+j],-20.f),20.f);
        float cv=fminf(fmaxf(comp[((size_t)(b*NN)+i2)*NN+j0+j],-20.f),20.f);
        float sb=1.f/(1.f+__expf(-bv)), sc=1.f/(1.f+__expf(-cv));
        *(uint32_t*)(sm+OFF_SCF+(j*2+0)*4)=f2bf(bv,sb);
        *(uint32_t*)(sm+OFF_SCF+(j*2+1)*4)=f2bf(cv,sc);
      }
    }
    __syncthreads();
  }
}

// ---- Kernel 3: symmetrize + diagonal ----
__global__ void symmetrize(float* __restrict__ out){
  int idx=blockIdx.x*256+threadIdx.x;
  int b=idx>>16, r=idx&65535, i=r>>8, j=r&255;
  float* ob=out+(size_t)b*NN*NN;
  if(j>i){
    float v=0.5f*(ob[i*NN+j]+ob[j*NN+i]);
    ob[i*NN+j]=v; ob[j*NN+i]=v;
  } else if(j==i) ob[i*NN+i]=-1e9f;
}

extern "C" void kernel_launch(void* const* d_in, const int* in_sizes, int n_in,
                              void* d_out, int out_size){
  const float* X   =(const float*)d_in[0];
  const float* base=(const float*)d_in[1];
  const float* comp=(const float*)d_in[2];
  const float* W1  =(const float*)d_in[3];
  const float* b1  =(const float*)d_in[4];
  const float* W2  =(const float*)d_in[5];
  const float* b2  =(const float*)d_in[6];
  float* out=(float*)d_out;

  cudaFuncSetAttribute(precompute_ab,cudaFuncAttributeMaxDynamicSharedMemorySize,PRE_SMEM);
  precompute_ab<<<NB*NN/4,256,PRE_SMEM>>>(X,W1,b1);
  cudaFuncSetAttribute(pair_gemm,cudaFuncAttributeMaxDynamicSharedMemorySize,SMEM_TOT);
  dim3 g(2,16,NB);
  pair_gemm<<<g,512,SMEM_TOT>>>(X,base,comp,W1,W2,b2,out);
  symmetrize<<<NB*NN*NN/256,256>>>(out);
}

// round 17
// speedup vs baseline: 1.3755x; 1.3755x over previous
#include <cuda_runtime.h>
#include <cuda_bf16.h>
#include <cstdint>

#define NB 4
#define NN 256
#define HH 128
typedef unsigned long long ull;

__device__ float g_A[NB*NN*HH];
__device__ float g_Bv[NB*NN*HH];

// smem byte offsets (pair_gemm)
#define OFF_W    0          // Wt image [128 h][288 k] bf16 swizzled, stride 576B
#define OFF_XJ   73728      // Xj bf16 pairs u32 [64 kp][136 stride]
#define OFF_BJ   108544     // Bj bf16 pairs u32 [128 j][66]
#define OFF_AJ   142336     // Aj bf16 pairs u32 [128 j][66]
#define OFF_HIS  176128     // hi bf16 pairs u32 [64]
#define OFF_AI   176384     // f32[128]
#define OFF_BI   176896     // f32[128]
#define OFF_W2   177408     // f32[128]
#define OFF_WS   177920     // f32[4][128] (W1 rows 512..515)
#define OFF_SCF  179968     // u32 [128 j][2]  scalars (i,j) bf16 pairs (GEMM k16)
#define OFF_SCD  180992     // f32 [128 j][4]  delta scalars (j,i)-(i,j)
#define OFF_RED  183040     // f32 P[128][2] then Q[128][2]
#define SMEM_TOT 185088

__device__ __forceinline__ uint32_t s32(const void* p){
  uint32_t a; asm("{ .reg .u64 t; cvta.to.shared.u64 t, %1; cvt.u32.u64 %0, t; }":"=r"(a):"l"(p)); return a;
}
__device__ __forceinline__ uint32_t foff(uint32_t r, uint32_t k){
  return ((r*576u + k*2u) ^ ((r&7u)<<4));
}
__device__ __forceinline__ uint32_t f2bf(float a,float b){
  __nv_bfloat162 t=__floats2bfloat162_rn(a,b); return *(uint32_t*)&t;
}
__device__ __forceinline__ uint32_t habsub2(uint32_t h,uint32_t x){
  __nv_bfloat162 r=__habs2(__hsub2(*(__nv_bfloat162*)&h,*(__nv_bfloat162*)&x));
  return *(uint32_t*)&r;
}
__device__ __forceinline__ uint32_t hmul2u(uint32_t h,uint32_t x){
  __nv_bfloat162 r=__hmul2(*(__nv_bfloat162*)&h,*(__nv_bfloat162*)&x);
  return *(uint32_t*)&r;
}
__device__ __forceinline__ void cpa16(void* dst,const void* src){
  unsigned d=(unsigned)__cvta_generic_to_shared(dst);
  asm volatile("cp.async.cg.shared.global [%0],[%1],16;\n"::"r"(d),"l"(src));
}
__device__ __forceinline__ void cpcommit(){ asm volatile("cp.async.commit_group;\n"); }

#define LDSM4(r0,r1,r2,r3,a) asm volatile( \
  "ldmatrix.sync.aligned.m8n8.x4.shared.b16 {%0,%1,%2,%3},[%4];" \
  :"=r"(r0),"=r"(r1),"=r"(r2),"=r"(r3):"r"(a))
#define MMA16816(c,a,b) asm volatile( \
  "mma.sync.aligned.m16n8k16.row.col.f32.bf16.bf16.f32 " \
  "{%0,%1,%2,%3},{%4,%5,%6,%7},{%8,%9},{%0,%1,%2,%3};" \
  :"+f"((c)[0]),"+f"((c)[1]),"+f"((c)[2]),"+f"((c)[3]) \
  :"r"((a)[0]),"r"((a)[1]),"r"((a)[2]),"r"((a)[3]),"r"((b)[0]),"r"((b)[1]))

extern __shared__ __align__(1024) char dynsm[];

// ---- Kernel 1: per-node halves (validated) ----
#define PRE_SMEM (4*HH*4 + 2*2*32*HH*4)
__global__ void __launch_bounds__(256)
precompute_ab(const float* __restrict__ X,
              const float* __restrict__ W1,
              const float* __restrict__ b1){
  float* Xs=(float*)dynsm;
  float* Ws=(float*)(dynsm+4*HH*4);
  int r0=blockIdx.x*4;
  int tid=threadIdx.x;
  int h=tid&127, s=tid>>7;

  for(int e=tid;e<4*HH/4;e+=256)
    ((float4*)Xs)[e]=((const float4*)(X+(size_t)r0*HH))[e];

  #define STAGE(c,buf) do{ \
    for(int e=tid;e<2*32*HH/4;e+=256){ \
      int sh=e>=(32*HH/4); int le=e-sh*(32*HH/4); \
      cpa16((float4*)(Ws+(buf)*2*32*HH+sh*32*HH)+le, \
            (const float4*)(W1+((size_t)(sh*HH+(c)*32))*HH)+le); \
    } cpcommit(); }while(0)

  STAGE(0,0);
  float acc[4]={0.f,0.f,0.f,0.f};
  for(int c=0;c<4;c++){
    if(c<3){ STAGE(c+1,(c+1)&1); asm volatile("cp.async.wait_group 1;\n"); }
    else   { asm volatile("cp.async.wait_group 0;\n"); }
    __syncthreads();
    const float* wp=Ws+(c&1)*2*32*HH+s*32*HH;
#pragma unroll 8
    for(int kk=0;kk<32;kk++){
      float wv=wp[kk*HH+h];
      int k=c*32+kk;
#pragma unroll
      for(int r=0;r<4;r++) acc[r]+=Xs[r*HH+k]*wv;
    }
    __syncthreads();
  }
  if(s==0){
    float bb=b1[h];
#pragma unroll
    for(int r=0;r<4;r++) g_A[(size_t)(r0+r)*HH+h]=acc[r]+bb;
  } else {
#pragma unroll
    for(int r=0;r<4;r++) g_Bv[(size_t)(r0+r)*HH+h]=acc[r];
  }
  #undef STAGE
}

// ---- Kernel 2: bf16 HMMA GEMM, triangular-pruned, dual-orientation epilogue ----
__global__ void __launch_bounds__(256,1)
pair_gemm(const float* __restrict__ X,const float* __restrict__ base,
          const float* __restrict__ comp,const float* __restrict__ W1,
          const float* __restrict__ W2,const float* __restrict__ b2,
          float* __restrict__ out){
  char* sm=dynsm;
  uint32_t smb=s32(sm);
  int tid=threadIdx.x, w=tid>>5, lane=tid&31;
  int b=blockIdx.z;
  // chunk mapping: 12 chunks for jt=0 (i<128), 24 chunks for jt=1 (i<256)
  int cid=blockIdx.x;
  int jt   = (cid<12)?0:1;
  int chunk= (cid<12)?cid:(cid-12);
  int i0b  = chunk*11;
  int ni   = jt? ((256-i0b<11)?(256-i0b):11) : ((128-i0b<11)?(128-i0b):11);
  int j0=jt*128;
  int jw=(w&3)*32, hw=(w>>2)*64;
  int qr=lane>>2, tql=lane&3;
  float b2v=b2[0];
  const float* baseb=base+(size_t)b*NN*NN;
  const float* compb=comp+(size_t)b*NN*NN;
  float* ob=out+(size_t)b*NN*NN;

  // ---- once: W image ----
  {
    int h=tid&127, halfk=tid>>7;
    for(int c8=0;c8<16;c8++){
      int k0=halfk*128+c8*8;
      uint32_t v[4];
#pragma unroll
      for(int q=0;q<4;q++)
        v[q]=f2bf(W1[(256+k0+2*q)*HH+h], W1[(256+k0+2*q+1)*HH+h]);
      *(float4*)(sm+OFF_W+foff(h,k0))=*(float4*)v;
    }
    if(tid<128){
      uint32_t v[4]={f2bf(W1[512*HH+h],W1[513*HH+h]),
                     f2bf(W1[514*HH+h],W1[515*HH+h]),0u,0u};
      *(float4*)(sm+OFF_W+foff(h,256))=*(float4*)v;
      uint32_t z[4]={0u,0u,0u,0u};
      *(float4*)(sm+OFF_W+foff(h,264))=*(float4*)z;
    }
  }
  // ---- once: Xj [kp][j] s136, Bj/Aj [j][hp] s66, W2, WS ----
  for(int idx=tid;idx<64*128;idx+=256){
    int kp=idx&63, j=idx>>6;
    float2 xv=*(const float2*)(X+(size_t)(b*NN+j0+j)*HH+2*kp);
    *(uint32_t*)(sm+OFF_XJ+(kp*136+j)*4)=f2bf(xv.x,xv.y);
  }
  for(int idx=tid;idx<64*128;idx+=256){
    int hp=idx&63, j=idx>>6;
    float2 bv=*(const float2*)(g_Bv+(size_t)(b*NN+j0+j)*HH+2*hp);
    *(uint32_t*)(sm+OFF_BJ+(j*66+hp)*4)=f2bf(bv.x,bv.y);
    float2 av=*(const float2*)(g_A+(size_t)(b*NN+j0+j)*HH+2*hp);
    *(uint32_t*)(sm+OFF_AJ+(j*66+hp)*4)=f2bf(av.x,av.y);
  }
  if(tid<32) ((float4*)(sm+OFF_W2))[tid]=((const float4*)W2)[tid];
  if(tid<128){
#pragma unroll
    for(int k=0;k<4;k++)
      *(float*)(sm+OFF_WS+(k*128+tid)*4)=W1[(512+k)*HH+tid];
  }

  // ---- stage first i ----
  {
    int i=i0b;
    if(tid<128){
      int j=tid;
      float bv1=fminf(fmaxf(baseb[(size_t)i*NN+j0+j],-20.f),20.f);
      float cv1=fminf(fmaxf(compb[(size_t)i*NN+j0+j],-20.f),20.f);
      float sb1=1.f/(1.f+__expf(-bv1)), sc1=1.f/(1.f+__expf(-cv1));
      *(uint32_t*)(sm+OFF_SCF+(j*2+0)*4)=f2bf(bv1,sb1);
      *(uint32_t*)(sm+OFF_SCF+(j*2+1)*4)=f2bf(cv1,sc1);
      float bv2=fminf(fmaxf(baseb[(size_t)(j0+j)*NN+i],-20.f),20.f);
      float cv2=fminf(fmaxf(compb[(size_t)(j0+j)*NN+i],-20.f),20.f);
      float sb2=1.f/(1.f+__expf(-bv2)), sc2=1.f/(1.f+__expf(-cv2));
      *(float4*)(sm+OFF_SCD+j*16)=make_float4(bv2-bv1,sb2-sb1,cv2-cv1,sc2-sc1);
    } else {
      int t=tid-128;
      if(t<64){
        float2 xv=*(const float2*)(X+(size_t)(b*NN+i)*HH+2*t);
        *(uint32_t*)(sm+OFF_HIS+t*4)=f2bf(xv.x,xv.y);
      } else if(t<96){
        ((float4*)(sm+OFF_AI))[t-64]=((const float4*)(g_A+(size_t)(b*NN+i)*HH))[t-64];
      } else {
        ((float4*)(sm+OFF_BI))[t-96]=((const float4*)(g_Bv+(size_t)(b*NN+i)*HH))[t-96];
      }
    }
  }
  __syncthreads();

  uint32_t xr=(uint32_t)((lane&7)<<4);
  uint32_t offB[4];
#pragma unroll
  for(int q=0;q<4;q++){
    uint32_t rB=(uint32_t)(hw + q*16 + (lane&7) + ((lane>>4)<<3));
    offB[q]= OFF_W + rB*576u + (uint32_t)(((lane>>3)&1)*16);
  }

  for(int itn=0;itn<ni;itn++){
    int i=i0b+itn;

    float c[2][8][4];
#pragma unroll
    for(int mt=0;mt<2;mt++)
#pragma unroll
      for(int nt=0;nt<8;nt++)
#pragma unroll
        for(int e=0;e<4;e++) c[mt][nt][e]=0.f;

    uint32_t a[2][2][4], bfr[2][8][2];

    #define MAKEA(ks,buf) do{ \
      int kp0=8*((ks)&7)+tql; \
      uint32_t h0=*(uint32_t*)(sm+OFF_HIS+kp0*4); \
      uint32_t h1=*(uint32_t*)(sm+OFF_HIS+(kp0+4)*4); \
      _Pragma("unroll") \
      for(int mt=0;mt<2;mt++){ \
        int r=jw+qr+mt*16; \
        uint32_t x0=*(uint32_t*)(sm+OFF_XJ+(kp0*136+r)*4); \
        uint32_t x1=*(uint32_t*)(sm+OFF_XJ+(kp0*136+r+8)*4); \
        uint32_t x2=*(uint32_t*)(sm+OFF_XJ+((kp0+4)*136+r)*4); \
        uint32_t x3=*(uint32_t*)(sm+OFF_XJ+((kp0+4)*136+r+8)*4); \
        if((ks)<8){ \
          a[buf][mt][0]=habsub2(h0,x0); a[buf][mt][1]=habsub2(h0,x1); \
          a[buf][mt][2]=habsub2(h1,x2); a[buf][mt][3]=habsub2(h1,x3); \
        } else { \
          a[buf][mt][0]=hmul2u(h0,x0); a[buf][mt][1]=hmul2u(h0,x1); \
          a[buf][mt][2]=hmul2u(h1,x2); a[buf][mt][3]=hmul2u(h1,x3); \
        } \
      } \
    }while(0)

    #define MAKEA16(buf) do{ \
      _Pragma("unroll") \
      for(int mt=0;mt<2;mt++){ \
        int r=jw+qr+mt*16; \
        a[buf][mt][0]=(tql<2)?*(uint32_t*)(sm+OFF_SCF+(r*2+tql)*4):0u; \
        a[buf][mt][1]=(tql<2)?*(uint32_t*)(sm+OFF_SCF+((r+8)*2+tql)*4):0u; \
        a[buf][mt][2]=0u; a[buf][mt][3]=0u; \
      } \
    }while(0)

    #define LOADB(ks,buf) do{ uint32_t k2=(uint32_t)(ks)*32u; \
      LDSM4(bfr[buf][0][0],bfr[buf][0][1],bfr[buf][1][0],bfr[buf][1][1], smb+((offB[0]+k2)^xr)); \
      LDSM4(bfr[buf][2][0],bfr[buf][2][1],bfr[buf][3][0],bfr[buf][3][1], smb+((offB[1]+k2)^xr)); \
      LDSM4(bfr[buf][4][0],bfr[buf][4][1],bfr[buf][5][0],bfr[buf][5][1], smb+((offB[2]+k2)^xr)); \
      LDSM4(bfr[buf][6][0],bfr[buf][6][1],bfr[buf][7][0],bfr[buf][7][1], smb+((offB[3]+k2)^xr)); \
    }while(0)

    MAKEA(0,0);
    LOADB(0,0);
#pragma unroll
    for(int ks=0;ks<17;ks++){
      int cur=ks&1, nxt=cur^1;
      if(ks<15)       MAKEA(ks+1,nxt);
      else if(ks==15) MAKEA16(nxt);
      if(ks<16)       LOADB(ks+1,nxt);
#pragma unroll
      for(int mt=0;mt<2;mt++)
#pragma unroll
        for(int nt=0;nt<8;nt++)
          MMA16816(c[mt][nt],a[cur][mt],bfr[cur][nt]);
    }
    #undef MAKEA
    #undef MAKEA16
    #undef LOADB

    // ---- dual-orientation epilogue ----
    {
      int ch=hw>>6;
      float p[4],q[4];
#pragma unroll
      for(int r=0;r<4;r++){ p[r]=0.f; q[r]=0.f; }
      float4 sd[4];
#pragma unroll
      for(int mt=0;mt<2;mt++)
#pragma unroll
        for(int rh=0;rh<2;rh++)
          sd[mt*2+rh]=*(float4*)(sm+OFF_SCD+(jw+mt*16+rh*8+qr)*16);
#pragma unroll
      for(int nt=0;nt<8;nt++){
        int hb=hw+nt*8+2*tql;
        float2 ai=*(float2*)(sm+OFF_AI+hb*4);
        float2 bi=*(float2*)(sm+OFF_BI+hb*4);
        float2 w2=*(float2*)(sm+OFF_W2+hb*4);
        float2 ws0=*(float2*)(sm+OFF_WS+hb*4);
        float2 ws1=*(float2*)(sm+OFF_WS+(128+hb)*4);
        float2 ws2=*(float2*)(sm+OFF_WS+(256+hb)*4);
        float2 ws3=*(float2*)(sm+OFF_WS+(384+hb)*4);
#pragma unroll
        for(int mt=0;mt<2;mt++){
#pragma unroll
          for(int rh=0;rh<2;rh++){
            int r=mt*2+rh;
            int j=jw+mt*16+rh*8+qr;
            float2 bj=__bfloat1622float2(*(__nv_bfloat162*)(sm+OFF_BJ+(j*66+(hb>>1))*4));
            float2 aj=__bfloat1622float2(*(__nv_bfloat162*)(sm+OFF_AJ+(j*66+(hb>>1))*4));
            float c0=c[mt][nt][rh*2], c1=c[mt][nt][rh*2+1];
            p[r]+=fmaxf(c0+ai.x+bj.x,0.f)*w2.x+fmaxf(c1+ai.y+bj.y,0.f)*w2.y;
            float dsx=sd[r].x*ws0.x+sd[r].y*ws1.x+sd[r].z*ws2.x+sd[r].w*ws3.x;
            float dsy=sd[r].x*ws0.y+sd[r].y*ws1.y+sd[r].z*ws2.y+sd[r].w*ws3.y;
            q[r]+=fmaxf(c0+dsx+aj.x+bi.x,0.f)*w2.x+fmaxf(c1+dsy+aj.y+bi.y,0.f)*w2.y;
          }
        }
      }
#pragma unroll
      for(int r=0;r<4;r++){
        p[r]+=__shfl_xor_sync(0xffffffffu,p[r],1);
        p[r]+=__shfl_xor_sync(0xffffffffu,p[r],2);
        q[r]+=__shfl_xor_sync(0xffffffffu,q[r],1);
        q[r]+=__shfl_xor_sync(0xffffffffu,q[r],2);
      }
      if(tql==0){
#pragma unroll
        for(int r=0;r<4;r++){
          int j=jw+(r>>1)*16+(r&1)*8+qr;
          *(float*)(sm+OFF_RED+(j*2+ch)*4)=p[r];
          *(float*)(sm+OFF_RED+1024+(j*2+ch)*4)=q[r];
        }
      }
    }
    __syncthreads();

    // writeback(i)+scalar-stage(i+1) on tid<128; HIS/AI/BI(i+1) on tid>=128
    if(tid<128){
      int j=tid, gj=j0+j;
      float vP=*(float*)(sm+OFF_RED+j*8)+*(float*)(sm+OFF_RED+j*8+4)+b2v;
      float vQ=*(float*)(sm+OFF_RED+1024+j*8)+*(float*)(sm+OFF_RED+1024+j*8+4)+b2v;
      if(gj>i){ float v=0.5f*(vP+vQ); ob[(size_t)i*NN+gj]=v; ob[(size_t)gj*NN+i]=v; }
      else if(gj==i) ob[(size_t)i*NN+i]=-1e9f;
      if(itn+1<ni){
        int i2=i+1;
        float bv1=fminf(fmaxf(baseb[(size_t)i2*NN+j0+j],-20.f),20.f);
        float cv1=fminf(fmaxf(compb[(size_t)i2*NN+j0+j],-20.f),20.f);
        float sb1=1.f/(1.f+__expf(-bv1)), sc1=1.f/(1.f+__expf(-cv1));
        *(uint32_t*)(sm+OFF_SCF+(j*2+0)*4)=f2bf(bv1,sb1);
        *(uint32_t*)(sm+OFF_SCF+(j*2+1)*4)=f2bf(cv1,sc1);
        float bv2=fminf(fmaxf(baseb[(size_t)(j0+j)*NN+i2],-20.f),20.f);
        float cv2=fminf(fmaxf(compb[(size_t)(j0+j)*NN+i2],-20.f),20.f);
        float sb2=1.f/(1.f+__expf(-bv2)), sc2=1.f/(1.f+__expf(-cv2));
        *(float4*)(sm+OFF_SCD+j*16)=make_float4(bv2-bv1,sb2-sb1,cv2-cv1,sc2-sc1);
      }
    } else if(itn+1<ni){
      int i2=i+1, t=tid-128;
      if(t<64){
        float2 xv=*(const float2*)(X+(size_t)(b*NN+i2)*HH+2*t);
        *(uint32_t*)(sm+OFF_HIS+t*4)=f2bf(xv.x,xv.y);
      } else if(t<96){
        ((float4*)(sm+OFF_AI))[t-64]=((const float4*)(g_A+(size_t)(b*NN+i2)*HH))[t-64];
      } else {
        ((float4*)(sm+OFF_BI))[t-96]=((const float4*)(g_Bv+(size_t)(b*NN+i2)*HH))[t-96];
      }
    }
    __syncthreads();
  }
}

extern "C" void kernel_launch(void* const* d_in, const int* in_sizes, int n_in,
                              void* d_out, int out_size){
  const float* X   =(const float*)d_in[0];
  const float* base=(const float*)d_in[1];
  const float* comp=(const float*)d_in[2];
  const float* W1  =(const float*)d_in[3];
  const float* b1  =(const float*)d_in[4];
  const float* W2  =(const float*)d_in[5];
  const float* b2  =(const float*)d_in[6];
  float* out=(float*)d_out;

  cudaFuncSetAttribute(precompute_ab,cudaFuncAttributeMaxDynamicSharedMemorySize,PRE_SMEM);
  precompute_ab<<<NB*NN/4,256,PRE_SMEM>>>(X,W1,b1);
  cudaFuncSetAttribute(pair_gemm,cudaFuncAttributeMaxDynamicSharedMemorySize,SMEM_TOT);
  dim3 g(36,1,NB);
  pair_gemm<<<g,256,SMEM_TOT>>>(X,base,comp,W1,W2,b2,out);
}